// round 15
// baseline (speedup 1.0000x reference)
#include <cuda_runtime.h>
#include <cuda_bf16.h>
#include <cfloat>
#include <cstdint>
#include <cstddef>

#define NPTS 2048
#define BATCH 4
#define KNN 20
#define CAP 256
#define SLOTS 8

// ---------------- scratch (device globals; no allocation allowed) ----------
__device__ float g_x0[BATCH * 3 * NPTS];
__device__ float g_xcat[(size_t)BATCH * 512 * NPTS];     // fp32 concat feats
__device__ uint16_t g_x0h[BATCH * 16 * NPTS];            // bf16 hi of x0, Cpad=16
__device__ uint16_t g_x0l[BATCH * 16 * NPTS];            // bf16 lo
__device__ uint16_t g_ch[(size_t)BATCH * 512 * NPTS];    // bf16 hi of xcat
__device__ uint16_t g_cl[(size_t)BATCH * 512 * NPTS];    // bf16 lo
__device__ uint16_t g_w5h[1024 * 512];
__device__ uint16_t g_w5l[1024 * 512];
__device__ float g_xx[BATCH * NPTS];
__device__ float g_D[(size_t)BATCH * NPTS * NPTS];       // 64 MB
__device__ float g_smax[(size_t)BATCH * NPTS * 32];      // per-row 64-col chunk maxes
__device__ int   g_knn[BATCH * NPTS * KNN];
__device__ int   g_cnt[BATCH * NPTS];
__device__ float g_Y[BATCH * NPTS * 256];
__device__ float g_Z[BATCH * NPTS * 256];
__device__ float g_pmax[BATCH * 16 * 1024];              // conv5 partial max
__device__ float g_psum[BATCH * 16 * 1024];              // conv5 partial sum
__device__ float g_f[BATCH * 2048];
__device__ float g_fc1[BATCH * 512];

__device__ __forceinline__ float lrelu(float v) { return v > 0.f ? v : 0.2f * v; }
#define BN_RSQ 0.99999500003749968750f
#define CAT_BSTR (512 * NPTS)
#define LDA 136   /* [k][m] tile row stride (halves) */
#define LDB 24    /* conv5 W tile [o][k] row stride (halves) */

__device__ __forceinline__ void split_bf16(float x, uint16_t& h, uint16_t& l) {
    __nv_bfloat16 bh = __float2bfloat16(x);
    float r = x - __bfloat162float(bh);
    __nv_bfloat16 bl = __float2bfloat16(r);
    h = *reinterpret_cast<uint16_t*>(&bh);
    l = *reinterpret_cast<uint16_t*>(&bl);
}

__device__ __forceinline__ void mma_bf16(float c[4], const uint32_t a[4],
                                         uint32_t b0, uint32_t b1) {
    asm volatile(
        "mma.sync.aligned.m16n8k16.row.col.f32.bf16.bf16.f32 "
        "{%0,%1,%2,%3}, {%4,%5,%6,%7}, {%8,%9}, {%0,%1,%2,%3};"
        : "+f"(c[0]), "+f"(c[1]), "+f"(c[2]), "+f"(c[3])
        : "r"(a[0]), "r"(a[1]), "r"(a[2]), "r"(a[3]), "r"(b0), "r"(b1));
}

__device__ __forceinline__ uint32_t sptr(const void* p) {
    return (uint32_t)__cvta_generic_to_shared(p);
}
__device__ __forceinline__ void ldsm4t(uint32_t& r0, uint32_t& r1,
                                       uint32_t& r2, uint32_t& r3, uint32_t a) {
    asm volatile("ldmatrix.sync.aligned.m8n8.x4.trans.shared.b16 {%0,%1,%2,%3}, [%4];"
                 : "=r"(r0), "=r"(r1), "=r"(r2), "=r"(r3) : "r"(a));
}
__device__ __forceinline__ void ldsm4(uint32_t& r0, uint32_t& r1,
                                      uint32_t& r2, uint32_t& r3, uint32_t a) {
    asm volatile("ldmatrix.sync.aligned.m8n8.x4.shared.b16 {%0,%1,%2,%3}, [%4];"
                 : "=r"(r0), "=r"(r1), "=r"(r2), "=r"(r3) : "r"(a));
}

// ---------------- transpose points + bf16 split (Cpad=16) ------------------
__global__ void k_transpose(const float* __restrict__ pts) {
    int i = blockIdx.x * blockDim.x + threadIdx.x;
    if (i < BATCH * NPTS) {
        int b = i / NPTS, n = i % NPTS;
        #pragma unroll
        for (int c = 0; c < 3; c++) {
            float v = pts[(b * NPTS + n) * 3 + c];
            g_x0[(b * 3 + c) * NPTS + n] = v;
            uint16_t h, l;
            split_bf16(v, h, l);
            g_x0h[(b * 16 + c) * NPTS + n] = h;
            g_x0l[(b * 16 + c) * NPTS + n] = l;
        }
        #pragma unroll
        for (int c = 3; c < 16; c++) {
            g_x0h[(b * 16 + c) * NPTS + n] = 0;
            g_x0l[(b * 16 + c) * NPTS + n] = 0;
        }
    }
}

// ---------------- row norms (fp32 exact) -----------------------------------
__global__ void k_xx(const float* __restrict__ feat, int C, int bstr) {
    int i = blockIdx.x * blockDim.x + threadIdx.x;
    if (i < BATCH * NPTS) {
        int b = i / NPTS, n = i % NPTS;
        const float* f = feat + (size_t)b * bstr + n;
        float s = 0.f;
        for (int c = 0; c < C; c++) { float v = f[(size_t)c * NPTS]; s = fmaf(v, v, s); }
        g_xx[i] = s;
    }
}

// ---------------- w5 bf16 split --------------------------------------------
__global__ void k_cvt_w5(const float* __restrict__ w5) {
    int i = blockIdx.x * blockDim.x + threadIdx.x;
    if (i < 1024 * 512) {
        uint16_t h, l;
        split_bf16(w5[i], h, l);
        g_w5h[i] = h; g_w5l[i] = l;
    }
}

// ---------------- distance GEMM via split-bf16 mma + ldmatrix --------------
// Also emits per-row 64-col chunk maxes to g_smax (for single-pass topk).
__global__ __launch_bounds__(256, 2) void k_dist_mma(
        const uint16_t* __restrict__ srch, const uint16_t* __restrict__ srcl,
        int Ceff, int bstr) {
    __shared__ uint16_t Ah[16 * LDA], Al[16 * LDA];
    __shared__ uint16_t Bh[16 * LDA], Bl[16 * LDA];
    const unsigned FULL = 0xffffffffu;
    int b = blockIdx.z;
    int i0 = blockIdx.y * 128, j0 = blockIdx.x * 128;
    const uint16_t* ph = srch + (size_t)b * bstr;
    const uint16_t* pl = srcl + (size_t)b * bstr;
    int tid = threadIdx.x, lane = tid & 31, warp = tid >> 5;
    int wm = warp & 3, wn = warp >> 2;
    int sub = lane >> 3, Lr = lane & 7;
    float acc[2][8][4];
    #pragma unroll
    for (int mt = 0; mt < 2; mt++)
        #pragma unroll
        for (int nt = 0; nt < 8; nt++)
            #pragma unroll
            for (int q = 0; q < 4; q++) acc[mt][nt][q] = 0.f;

    for (int c0 = 0; c0 < Ceff; c0 += 16) {
        #pragma unroll
        for (int m = 0; m < 4; m++) {
            int idx = m * 256 + tid;
            int mat = idx >> 8, r = (idx >> 4) & 15, q = idx & 15;
            const uint16_t* src = (mat & 1) ? pl : ph;
            int base = (mat & 2) ? j0 : i0;
            uint16_t* dst = (mat == 0) ? Ah : (mat == 1) ? Al : (mat == 2) ? Bh : Bl;
            *(uint4*)&dst[r * LDA + q * 8] =
                *(const uint4*)&src[(size_t)(c0 + r) * NPTS + base + q * 8];
        }
        __syncthreads();
        #pragma unroll
        for (int pass = 0; pass < 3; pass++) {
            const uint16_t* A = (pass == 1) ? Al : Ah;
            const uint16_t* B = (pass == 2) ? Bl : Bh;
            uint32_t af[2][4];
            #pragma unroll
            for (int mt = 0; mt < 2; mt++) {
                int krow = ((sub & 2) ? 8 : 0) + Lr;
                int mcol = wm * 32 + mt * 16 + ((sub & 1) ? 8 : 0);
                ldsm4t(af[mt][0], af[mt][1], af[mt][2], af[mt][3],
                       sptr(A + krow * LDA + mcol));
            }
            uint32_t bf[8][2];
            #pragma unroll
            for (int u = 0; u < 4; u++) {
                int krow = ((sub & 1) ? 8 : 0) + Lr;
                int ncol = wn * 64 + u * 16 + ((sub & 2) ? 8 : 0);
                uint32_t r0, r1, r2, r3;
                ldsm4t(r0, r1, r2, r3, sptr(B + krow * LDA + ncol));
                bf[2 * u][0] = r0; bf[2 * u][1] = r1;
                bf[2 * u + 1][0] = r2; bf[2 * u + 1][1] = r3;
            }
            #pragma unroll
            for (int nt = 0; nt < 8; nt++) {
                mma_bf16(acc[0][nt], af[0], bf[nt][0], bf[nt][1]);
                mma_bf16(acc[1][nt], af[1], bf[nt][0], bf[nt][1]);
            }
        }
        __syncthreads();
    }
    // epilogue: 2*acc - xi - xj -> g_D, plus warp 64-col chunk max -> g_smax
    int g = lane >> 2, t = lane & 3;
    #pragma unroll
    for (int mt = 0; mt < 2; mt++) {
        int r0 = i0 + wm * 32 + mt * 16 + g;
        int r1 = r0 + 8;
        float xi0 = g_xx[b * NPTS + r0];
        float xi1 = g_xx[b * NPTS + r1];
        float m0 = -FLT_MAX, m1 = -FLT_MAX;
        #pragma unroll
        for (int nt = 0; nt < 8; nt++) {
            int j = j0 + wn * 64 + nt * 8 + 2 * t;
            float xj0 = g_xx[b * NPTS + j];
            float xj1 = g_xx[b * NPTS + j + 1];
            float2 v0, v1;
            v0.x = 2.f * acc[mt][nt][0] - xi0 - xj0;
            v0.y = 2.f * acc[mt][nt][1] - xi0 - xj1;
            v1.x = 2.f * acc[mt][nt][2] - xi1 - xj0;
            v1.y = 2.f * acc[mt][nt][3] - xi1 - xj1;
            m0 = fmaxf(m0, fmaxf(v0.x, v0.y));
            m1 = fmaxf(m1, fmaxf(v1.x, v1.y));
            *(float2*)&g_D[((size_t)b * NPTS + r0) * NPTS + j] = v0;
            *(float2*)&g_D[((size_t)b * NPTS + r1) * NPTS + j] = v1;
        }
        m0 = fmaxf(m0, __shfl_xor_sync(FULL, m0, 1));
        m0 = fmaxf(m0, __shfl_xor_sync(FULL, m0, 2));
        m1 = fmaxf(m1, __shfl_xor_sync(FULL, m1, 1));
        m1 = fmaxf(m1, __shfl_xor_sync(FULL, m1, 2));
        if (t == 0) {
            int ch = (j0 >> 6) + wn;
            g_smax[(size_t)(b * NPTS + r0) * 32 + ch] = m0;
            g_smax[(size_t)(b * NPTS + r1) * 32 + ch] = m1;
        }
    }
}

// ---------------- conv5 via split-bf16 mma + fused partial pooling ---------
__global__ __launch_bounds__(256, 2) void k_conv5_mma(
        const float* __restrict__ gam, const float* __restrict__ bet) {
    __shared__ uint16_t Ah[16 * LDA], Al[16 * LDA];
    __shared__ uint16_t Bh[128 * LDB], Bl[128 * LDB];
    __shared__ float sm_max[8][64];
    __shared__ float sm_sum[8][64];
    const unsigned FULL = 0xffffffffu;
    int b = blockIdx.z;
    int n0 = blockIdx.x * 128, o0 = blockIdx.y * 128;
    const uint16_t* ph = g_ch + (size_t)b * CAT_BSTR;
    const uint16_t* pl = g_cl + (size_t)b * CAT_BSTR;
    int tid = threadIdx.x, lane = tid & 31, warp = tid >> 5;
    int wm = warp & 3, wn = warp >> 2;
    int sub = lane >> 3, Lr = lane & 7;
    float acc[2][8][4];
    #pragma unroll
    for (int mt = 0; mt < 2; mt++)
        #pragma unroll
        for (int nt = 0; nt < 8; nt++)
            #pragma unroll
            for (int q = 0; q < 4; q++) acc[mt][nt][q] = 0.f;

    for (int c0 = 0; c0 < 512; c0 += 16) {
        #pragma unroll
        for (int m = 0; m < 4; m++) {
            int idx = m * 256 + tid;
            if (idx < 512) {
                int mat = idx >> 8, r = (idx >> 4) & 15, q = idx & 15;
                const uint16_t* src = mat ? pl : ph;
                uint16_t* dst = mat ? Al : Ah;
                *(uint4*)&dst[r * LDA + q * 8] =
                    *(const uint4*)&src[(size_t)(c0 + r) * NPTS + n0 + q * 8];
            } else {
                int j = idx - 512;
                int mat = j >> 8, row = (j >> 1) & 127, q = j & 1;
                const uint16_t* src = mat ? g_w5l : g_w5h;
                uint16_t* dst = mat ? Bl : Bh;
                *(uint4*)&dst[row * LDB + q * 8] =
                    *(const uint4*)&src[(size_t)(o0 + row) * 512 + c0 + q * 8];
            }
        }
        __syncthreads();
        #pragma unroll
        for (int pass = 0; pass < 3; pass++) {
            const uint16_t* A = (pass == 1) ? Al : Ah;
            const uint16_t* B = (pass == 2) ? Bl : Bh;
            uint32_t af[2][4];
            #pragma unroll
            for (int mt = 0; mt < 2; mt++) {
                int krow = ((sub & 2) ? 8 : 0) + Lr;
                int mcol = wm * 32 + mt * 16 + ((sub & 1) ? 8 : 0);
                ldsm4t(af[mt][0], af[mt][1], af[mt][2], af[mt][3],
                       sptr(A + krow * LDA + mcol));
            }
            uint32_t bf[8][2];
            #pragma unroll
            for (int u = 0; u < 4; u++) {
                int orow = wn * 64 + u * 16 + ((sub & 2) ? 8 : 0) + Lr;
                int kcol = (sub & 1) ? 8 : 0;
                uint32_t r0, r1, r2, r3;
                ldsm4(r0, r1, r2, r3, sptr(B + orow * LDB + kcol));
                bf[2 * u][0] = r0; bf[2 * u][1] = r1;
                bf[2 * u + 1][0] = r2; bf[2 * u + 1][1] = r3;
            }
            #pragma unroll
            for (int nt = 0; nt < 8; nt++) {
                mma_bf16(acc[0][nt], af[0], bf[nt][0], bf[nt][1]);
                mma_bf16(acc[1][nt], af[1], bf[nt][0], bf[nt][1]);
            }
        }
        __syncthreads();
    }
    // epilogue: BN + lrelu, then per-block (max,sum) per channel
    int t = lane & 3;
    float pm[16], ps[16];
    #pragma unroll
    for (int i = 0; i < 16; i++) { pm[i] = -FLT_MAX; ps[i] = 0.f; }
    #pragma unroll
    for (int nt = 0; nt < 8; nt++) {
        int o = o0 + wn * 64 + nt * 8 + 2 * t;
        float sc0 = gam[o] * BN_RSQ, bi0 = bet[o];
        float sc1 = gam[o + 1] * BN_RSQ, bi1 = bet[o + 1];
        #pragma unroll
        for (int mt = 0; mt < 2; mt++) {
            float h0 = lrelu(fmaf(acc[mt][nt][0], sc0, bi0));
            float h1 = lrelu(fmaf(acc[mt][nt][1], sc1, bi1));
            float h2 = lrelu(fmaf(acc[mt][nt][2], sc0, bi0));
            float h3 = lrelu(fmaf(acc[mt][nt][3], sc1, bi1));
            pm[nt * 2] = fmaxf(pm[nt * 2], fmaxf(h0, h2));
            ps[nt * 2] += h0 + h2;
            pm[nt * 2 + 1] = fmaxf(pm[nt * 2 + 1], fmaxf(h1, h3));
            ps[nt * 2 + 1] += h1 + h3;
        }
    }
    #pragma unroll
    for (int i = 0; i < 16; i++) {
        #pragma unroll
        for (int off = 4; off <= 16; off <<= 1) {
            pm[i] = fmaxf(pm[i], __shfl_xor_sync(FULL, pm[i], off));
            ps[i] += __shfl_xor_sync(FULL, ps[i], off);
        }
    }
    if (lane < 4) {
        #pragma unroll
        for (int nt = 0; nt < 8; nt++) {
            #pragma unroll
            for (int p = 0; p < 2; p++) {
                int cc = nt * 8 + 2 * lane + p;
                sm_max[warp][cc] = pm[nt * 2 + p];
                sm_sum[warp][cc] = ps[nt * 2 + p];
            }
        }
    }
    __syncthreads();
    if (tid < 128) {
        int col = tid;
        int w0 = (col >> 6) * 4, cc = col & 63;
        float m = sm_max[w0][cc], s = sm_sum[w0][cc];
        #pragma unroll
        for (int w = 1; w < 4; w++) {
            m = fmaxf(m, sm_max[w0 + w][cc]);
            s += sm_sum[w0 + w][cc];
        }
        size_t base = (size_t)(b * 16 + blockIdx.x) * 1024 + o0 + col;
        g_pmax[base] = m;
        g_psum[base] = s;
    }
}

// ---------------- top-K main: deep-pipelined scan + per-lane-slot compact --
// Software pipeline depth 8 (MLP~8) + quad early-out (max4 >= Te gate).
// Candidate order irrelevant: select pops by exact (value desc, index asc).
__global__ __launch_bounds__(256) void k_topk() {
    __shared__ float sv[8][CAP];
    __shared__ int   si[8][CAP];
    const unsigned FULL = 0xffffffffu;
    int lane = threadIdx.x & 31, warp = threadIdx.x >> 5;
    int row = blockIdx.x * 8 + warp;
    const float4* drow4 = (const float4*)(g_D + (size_t)row * NPTS);

    // Te = 20th largest of 32 precomputed 64-col chunk maxes (<= true 20th)
    float v = g_smax[(size_t)row * 32 + lane];
    #pragma unroll
    for (int k = 2; k <= 32; k <<= 1) {
        #pragma unroll
        for (int j = k >> 1; j > 0; j >>= 1) {
            float o = __shfl_xor_sync(FULL, v, j);
            bool takeMax = (((lane & k) == 0) == ((lane & j) == 0));
            v = takeMax ? fmaxf(v, o) : fminf(v, o);
        }
    }
    float Te = __shfl_sync(FULL, v, KNN - 1);

    // pipelined scan: 8 float4 in flight; quad gate then per-elem append
    int c = 0;
    float4 buf[8];
    #pragma unroll
    for (int t = 0; t < 8; t++) buf[t] = drow4[t * 32 + lane];
    #pragma unroll
    for (int t = 0; t < 8; t++) {
        float4 q = buf[t];
        buf[t] = drow4[(t + 8) * 32 + lane];      // prefetch second half
        float m4 = fmaxf(fmaxf(q.x, q.y), fmaxf(q.z, q.w));
        if (m4 >= Te) {
            int jb = t * 128 + lane * 4;
            float vals[4] = {q.x, q.y, q.z, q.w};
            #pragma unroll
            for (int m = 0; m < 4; m++) {
                if (vals[m] >= Te) {
                    if (c < SLOTS) {
                        sv[warp][lane * SLOTS + c] = vals[m];
                        si[warp][lane * SLOTS + c] = jb + m;
                    }
                    c++;
                }
            }
        }
    }
    #pragma unroll
    for (int t = 0; t < 8; t++) {
        float4 q = buf[t];
        float m4 = fmaxf(fmaxf(q.x, q.y), fmaxf(q.z, q.w));
        if (m4 >= Te) {
            int jb = (t + 8) * 128 + lane * 4;
            float vals[4] = {q.x, q.y, q.z, q.w};
            #pragma unroll
            for (int m = 0; m < 4; m++) {
                if (vals[m] >= Te) {
                    if (c < SLOTS) {
                        sv[warp][lane * SLOTS + c] = vals[m];
                        si[warp][lane * SLOTS + c] = jb + m;
                    }
                    c++;
                }
            }
        }
    }
    unsigned ov = __ballot_sync(FULL, c > SLOTS);
    if (lane == 0) g_cnt[row] = ov ? (CAP + 1) : 0;
    __syncwarp();

    if (!ov) {
        float lv[SLOTS]; int li[SLOTS];
        #pragma unroll
        for (int q = 0; q < SLOTS; q++) {
            bool in = q < c;
            lv[q] = in ? sv[warp][lane * SLOTS + q] : -FLT_MAX;
            li[q] = in ? si[warp][lane * SLOTS + q] : 0x7FFFFFFF;
        }
        #pragma unroll 1
        for (int k = 0; k < KNN; k++) {
            float bv = -FLT_MAX; int bi = 0x7FFFFFFF, bq = 0;
            #pragma unroll
            for (int q = 0; q < SLOTS; q++) {
                if (lv[q] > bv || (lv[q] == bv && li[q] < bi)) {
                    bv = lv[q]; bi = li[q]; bq = q;
                }
            }
            float wv = bv; int wi = bi;
            #pragma unroll
            for (int s = 16; s > 0; s >>= 1) {
                float ovv = __shfl_xor_sync(FULL, wv, s);
                int   oi = __shfl_xor_sync(FULL, wi, s);
                if (ovv > wv || (ovv == wv && oi < wi)) { wv = ovv; wi = oi; }
            }
            if (lane == 0) g_knn[(size_t)row * KNN + k] = wi;
            if (bv == wv && bi == wi) { lv[bq] = -FLT_MAX; li[bq] = 0x7FFFFFFF; }
        }
    }
    // overflow rows handled by k_topk_fb
}

// ---------------- top-K fallback: exact full-row path (rarely runs) --------
__global__ void k_topk_fb() {
    const unsigned FULL = 0xffffffffu;
    int lane = threadIdx.x & 31, warp = threadIdx.x >> 5;
    int row = blockIdx.x * 8 + warp;
    if (g_cnt[row] <= CAP) return;      // warp-uniform: whole warp exits

    const float* drow = g_D + (size_t)row * NPTS;
    float arr[KNN]; int ai[KNN];
    #pragma unroll
    for (int q = 0; q < KNN; q++) { arr[q] = -FLT_MAX; ai[q] = 0x7FFFFFFF; }
    #pragma unroll 1
    for (int t = 0; t < NPTS / 128; t++) {
        int jb = t * 128 + lane * 4;
        float4 v4 = *(const float4*)&drow[jb];
        float vv[4] = {v4.x, v4.y, v4.z, v4.w};
        #pragma unroll
        for (int m = 0; m < 4; m++) {
            float vx = vv[m];
            if (vx > arr[0]) {
                arr[0] = vx; ai[0] = jb + m;
                #pragma unroll
                for (int q = 0; q < KNN - 1; q++) {
                    if (arr[q + 1] < arr[q]) {
                        float tv = arr[q]; arr[q] = arr[q + 1]; arr[q + 1] = tv;
                        int ti = ai[q]; ai[q] = ai[q + 1]; ai[q + 1] = ti;
                    }
                }
            }
        }
    }
    #pragma unroll 1
    for (int k = 0; k < KNN; k++) {
        float cvv = arr[KNN - 1]; int cii = ai[KNN - 1];
        float wv = cvv; int wi = cii;
        #pragma unroll
        for (int s = 16; s > 0; s >>= 1) {
            float ov = __shfl_xor_sync(FULL, wv, s);
            int   oi = __shfl_xor_sync(FULL, wi, s);
            if (ov > wv || (ov == wv && oi < wi)) { wv = ov; wi = oi; }
        }
        if (lane == 0) g_knn[(size_t)row * KNN + k] = wi;
        if (cii == wi) {
            #pragma unroll
            for (int q = KNN - 1; q > 0; q--) { arr[q] = arr[q - 1]; ai[q] = ai[q - 1]; }
            arr[0] = -FLT_MAX; ai[0] = 0x7FFFFFFF;
        }
    }
}

// ---------------- Y = W2 X, Z = (W1-W2) X (fp32) ---------------------------
__global__ void k_yz(const float* __restrict__ feat, const float* __restrict__ W,
                     int C, int Cout, int bstr) {
    __shared__ float As[16][64];
    __shared__ float B1[16][64];
    __shared__ float B2[16][64];
    int b = blockIdx.z;
    int n0 = blockIdx.x * 64, o0 = blockIdx.y * 64;
    const float* fb = feat + (size_t)b * bstr;
    int tx = threadIdx.x & 15, ty = threadIdx.x >> 4;
    float aU[4][4] = {}, aY[4][4] = {};
    for (int c0 = 0; c0 < C; c0 += 16) {
        for (int e = threadIdx.x; e < 1024; e += 256) {
            int kk = e >> 6, nn = e & 63;
            int c = c0 + kk;
            As[kk][nn] = (c < C) ? fb[(size_t)c * NPTS + n0 + nn] : 0.f;
        }
        for (int e = threadIdx.x; e < 1024; e += 256) {
            int kk = e & 15, oo = e >> 4;
            int c = c0 + kk;
            float w1 = 0.f, w2 = 0.f;
            if (c < C) {
                const float* wr = W + (size_t)(o0 + oo) * (2 * C);
                w1 = wr[c]; w2 = wr[C + c];
            }
            B1[kk][oo] = w1; B2[kk][oo] = w2;
        }
        __syncthreads();
        #pragma unroll
        for (int kk = 0; kk < 16; kk++) {
            float4 a4 = *(const float4*)&As[kk][ty * 4];
            float4 b14 = *(const float4*)&B1[kk][tx * 4];
            float4 b24 = *(const float4*)&B2[kk][tx * 4];
            float av[4] = {a4.x, a4.y, a4.z, a4.w};
            float b1v[4] = {b14.x, b14.y, b14.z, b14.w};
            float b2v[4] = {b24.x, b24.y, b24.z, b24.w};
            #pragma unroll
            for (int r = 0; r < 4; r++)
                #pragma unroll
                for (int s = 0; s < 4; s++) {
                    aU[r][s] = fmaf(av[r], b1v[s], aU[r][s]);
                    aY[r][s] = fmaf(av[r], b2v[s], aY[r][s]);
                }
        }
        __syncthreads();
    }
    #pragma unroll
    for (int r = 0; r < 4; r++) {
        int n = n0 + ty * 4 + r;
        size_t base = ((size_t)b * NPTS + n) * 256 + o0 + tx * 4;
        float4 y, z;
        y.x = aY[r][0]; y.y = aY[r][1]; y.z = aY[r][2]; y.w = aY[r][3];
        z.x = aU[r][0] - y.x; z.y = aU[r][1] - y.y;
        z.z = aU[r][2] - y.z; z.w = aU[r][3] - y.w;
        *(float4*)&g_Y[base] = y;
        *(float4*)&g_Z[base] = z;
    }
}

// ---------------- gather-max + BN + lrelu -> xcat + bf16 mirrors -----------
__global__ void k_gather(float* __restrict__ out, const float* __restrict__ gam,
                         const float* __restrict__ bet, int Cout, int co) {
    __shared__ int   sidx[32 * KNN];
    __shared__ float sout[256 * 33];
    int b = blockIdx.y, n0 = blockIdx.x * 32;
    for (int e = threadIdx.x; e < 32 * KNN; e += blockDim.x)
        sidx[e] = g_knn[((size_t)b * NPTS + n0) * KNN + e];
    __syncthreads();
    int o = threadIdx.x;
    float sc = gam[o] * BN_RSQ, bi = bet[o];
    const float* Yb = g_Y + (size_t)b * NPTS * 256;
    const float* Zb = g_Z + (size_t)b * NPTS * 256;
    for (int nn = 0; nn < 32; nn++) {
        float m = -FLT_MAX;
        #pragma unroll
        for (int k = 0; k < KNN; k++) {
            int j = sidx[nn * KNN + k];
            m = fmaxf(m, Yb[(size_t)j * 256 + o]);
        }
        float v = Zb[(size_t)(n0 + nn) * 256 + o] + m;
        v = lrelu(fmaf(v, sc, bi));
        sout[o * 33 + nn] = v;
    }
    __syncthreads();
    float* ob = out + (size_t)b * CAT_BSTR;
    for (int e = threadIdx.x; e < Cout * 32; e += blockDim.x) {
        int oo = e >> 5, nn = e & 31;
        float v = sout[oo * 33 + nn];
        ob[(size_t)oo * NPTS + n0 + nn] = v;
        uint16_t h, l;
        split_bf16(v, h, l);
        size_t bidx = ((size_t)b * 512 + co + oo) * NPTS + n0 + nn;
        g_ch[bidx] = h;
        g_cl[bidx] = l;
    }
}

// ---------------- final pool from conv5 partials -> g_f --------------------
__global__ void k_pool2() {
    int b = blockIdx.y;
    int o = blockIdx.x * 256 + threadIdx.x;
    float m = -FLT_MAX, s = 0.f;
    #pragma unroll
    for (int nt = 0; nt < 16; nt++) {
        size_t base = (size_t)(b * 16 + nt) * 1024 + o;
        m = fmaxf(m, g_pmax[base]);
        s += g_psum[base];
    }
    g_f[b * 2048 + o] = m;
    g_f[b * 2048 + 1024 + o] = s * (1.0f / NPTS);
}

// ---------------- fc1: 2048->512, BN + lrelu -------------------------------
__global__ void k_fc1(const float* __restrict__ fw, const float* __restrict__ fb,
                      const float* __restrict__ gam, const float* __restrict__ bet) {
    int b = blockIdx.y;
    int w = threadIdx.x >> 5, lane = threadIdx.x & 31;
    int o = blockIdx.x * 8 + w;
    const float* f = g_f + b * 2048;
    const float* wr = fw + (size_t)o * 2048;
    float acc = 0.f;
    for (int c = lane; c < 2048; c += 32) acc = fmaf(f[c], wr[c], acc);
    #pragma unroll
    for (int s = 16; s > 0; s >>= 1) acc += __shfl_xor_sync(0xffffffffu, acc, s);
    if (lane == 0) {
        float v = acc + fb[o];
        v = lrelu(fmaf(v, gam[o] * BN_RSQ, bet[o]));
        g_fc1[b * 512 + o] = v;
    }
}

// ---------------- fc2: 512->256, BN (no lrelu) -> d_out --------------------
__global__ void k_fc2(const float* __restrict__ fw, const float* __restrict__ fb,
                      const float* __restrict__ gam, const float* __restrict__ bet,
                      float* __restrict__ out) {
    int b = blockIdx.y;
    int w = threadIdx.x >> 5, lane = threadIdx.x & 31;
    int o = blockIdx.x * 8 + w;
    const float* f = g_fc1 + b * 512;
    const float* wr = fw + (size_t)o * 512;
    float acc = 0.f;
    for (int c = lane; c < 512; c += 32) acc = fmaf(f[c], wr[c], acc);
    #pragma unroll
    for (int s = 16; s > 0; s >>= 1) acc += __shfl_xor_sync(0xffffffffu, acc, s);
    if (lane == 0) {
        float v = acc + fb[o];
        out[b * 256 + o] = fmaf(v, gam[o] * BN_RSQ, bet[o]);
    }
}

// ---------------- driver ---------------------------------------------------
static void run_edge(const float* feat, int C, int bstr,
                     const uint16_t* dh, const uint16_t* dl, int Ceff, int bfstr,
                     const float* W, const float* gam, const float* bet,
                     float* out, int Cout, int co) {
    k_xx<<<(BATCH * NPTS + 255) / 256, 256>>>(feat, C, bstr);
    k_dist_mma<<<dim3(NPTS / 128, NPTS / 128, BATCH), 256>>>(dh, dl, Ceff, bfstr);
    k_topk<<<BATCH * NPTS / 8, 256>>>();
    k_topk_fb<<<BATCH * NPTS / 8, 256>>>();
    k_yz<<<dim3(NPTS / 64, Cout / 64, BATCH), 256>>>(feat, W, C, Cout, bstr);
    k_gather<<<dim3(NPTS / 32, BATCH), Cout>>>(out, gam, bet, Cout, co);
}

extern "C" void kernel_launch(void* const* d_in, const int* in_sizes, int n_in,
                              void* d_out, int out_size) {
    const float* pts = (const float*)d_in[0];
    const float* w1 = (const float*)d_in[1];
    const float* g1 = (const float*)d_in[2];
    const float* b1 = (const float*)d_in[3];
    const float* w2 = (const float*)d_in[4];
    const float* g2 = (const float*)d_in[5];
    const float* b2 = (const float*)d_in[6];
    const float* w3 = (const float*)d_in[7];
    const float* g3 = (const float*)d_in[8];
    const float* b3 = (const float*)d_in[9];
    const float* w4 = (const float*)d_in[10];
    const float* g4 = (const float*)d_in[11];
    const float* b4 = (const float*)d_in[12];
    const float* w5 = (const float*)d_in[13];
    const float* g5 = (const float*)d_in[14];
    const float* b5 = (const float*)d_in[15];
    const float* fw1 = (const float*)d_in[16];
    const float* fb1 = (const float*)d_in[17];
    const float* g6 = (const float*)d_in[18];
    const float* b6 = (const float*)d_in[19];
    const float* fw2 = (const float*)d_in[20];
    const float* fb2 = (const float*)d_in[21];
    const float* g7 = (const float*)d_in[22];
    const float* b7 = (const float*)d_in[23];

    float *x0, *xcat;
    uint16_t *x0h, *x0l, *ch, *cl;
    cudaGetSymbolAddress((void**)&x0, g_x0);
    cudaGetSymbolAddress((void**)&xcat, g_xcat);
    cudaGetSymbolAddress((void**)&x0h, g_x0h);
    cudaGetSymbolAddress((void**)&x0l, g_x0l);
    cudaGetSymbolAddress((void**)&ch, g_ch);
    cudaGetSymbolAddress((void**)&cl, g_cl);
    float* x1 = xcat;                  // ch 0..63
    float* x2 = xcat + 64 * NPTS;      // ch 64..127
    float* x3 = xcat + 128 * NPTS;     // ch 128..255
    float* x4 = xcat + 256 * NPTS;     // ch 256..511

    k_transpose<<<(BATCH * NPTS + 255) / 256, 256>>>(pts);
    run_edge(x0, 3,   3 * NPTS, x0h, x0l, 16, 16 * NPTS,
             w1, g1, b1, x1, 64, 0);
    run_edge(x1, 64,  CAT_BSTR, ch,              cl,              64,  CAT_BSTR,
             w2, g2, b2, x2, 64, 64);
    run_edge(x2, 64,  CAT_BSTR, ch + 64 * NPTS,  cl + 64 * NPTS,  64,  CAT_BSTR,
             w3, g3, b3, x3, 128, 128);
    run_edge(x3, 128, CAT_BSTR, ch + 128 * NPTS, cl + 128 * NPTS, 128, CAT_BSTR,
             w4, g4, b4, x4, 256, 256);
    k_cvt_w5<<<(1024 * 512 + 255) / 256, 256>>>(w5);
    k_conv5_mma<<<dim3(NPTS / 128, 1024 / 128, BATCH), 256>>>(g5, b5);
    k_pool2<<<dim3(1024 / 256, BATCH), 256>>>();
    k_fc1<<<dim3(512 / 8, BATCH), 256>>>(fw1, fb1, g6, b6);
    k_fc2<<<dim3(256 / 8, BATCH), 256>>>(fw2, fb2, g7, b7, (float*)d_out);
}

// round 16
// speedup vs baseline: 1.0352x; 1.0352x over previous
#include <cuda_runtime.h>
#include <cuda_bf16.h>
#include <cfloat>
#include <cstdint>
#include <cstddef>

#define NPTS 2048
#define BATCH 4
#define KNN 20
#define CAP 256
#define SLOTS 8

// ---------------- scratch (device globals; no allocation allowed) ----------
__device__ float g_x0[BATCH * 3 * NPTS];
__device__ float g_xcat[(size_t)BATCH * 512 * NPTS];     // fp32 concat feats
__device__ uint16_t g_x0h[BATCH * 16 * NPTS];            // bf16 hi of x0, Cpad=16
__device__ uint16_t g_x0l[BATCH * 16 * NPTS];            // bf16 lo
__device__ uint16_t g_ch[(size_t)BATCH * 512 * NPTS];    // bf16 hi of xcat
__device__ uint16_t g_cl[(size_t)BATCH * 512 * NPTS];    // bf16 lo
__device__ uint16_t g_w5h[1024 * 512];
__device__ uint16_t g_w5l[1024 * 512];
__device__ float g_xx[BATCH * NPTS];
__device__ float g_D[(size_t)BATCH * NPTS * NPTS];       // 64 MB
__device__ float g_smax[(size_t)BATCH * NPTS * 32];      // per-row 64-col chunk maxes
__device__ int   g_knn[BATCH * NPTS * KNN];
__device__ int   g_cnt[BATCH * NPTS];
__device__ float g_Y[BATCH * NPTS * 256];
__device__ float g_Z[BATCH * NPTS * 256];
__device__ float g_pmax[BATCH * 16 * 1024];              // conv5 partial max
__device__ float g_psum[BATCH * 16 * 1024];              // conv5 partial sum
__device__ float g_f[BATCH * 2048];
__device__ float g_fc1[BATCH * 512];

__device__ __forceinline__ float lrelu(float v) { return v > 0.f ? v : 0.2f * v; }
#define BN_RSQ 0.99999500003749968750f
#define CAT_BSTR (512 * NPTS)
#define LDA 136   /* [k][m] tile row stride (halves) */
#define LDB 24    /* conv5 W tile [o][k] row stride (halves) */

__device__ __forceinline__ void split_bf16(float x, uint16_t& h, uint16_t& l) {
    __nv_bfloat16 bh = __float2bfloat16(x);
    float r = x - __bfloat162float(bh);
    __nv_bfloat16 bl = __float2bfloat16(r);
    h = *reinterpret_cast<uint16_t*>(&bh);
    l = *reinterpret_cast<uint16_t*>(&bl);
}

__device__ __forceinline__ void mma_bf16(float c[4], const uint32_t a[4],
                                         uint32_t b0, uint32_t b1) {
    asm volatile(
        "mma.sync.aligned.m16n8k16.row.col.f32.bf16.bf16.f32 "
        "{%0,%1,%2,%3}, {%4,%5,%6,%7}, {%8,%9}, {%0,%1,%2,%3};"
        : "+f"(c[0]), "+f"(c[1]), "+f"(c[2]), "+f"(c[3])
        : "r"(a[0]), "r"(a[1]), "r"(a[2]), "r"(a[3]), "r"(b0), "r"(b1));
}

__device__ __forceinline__ uint32_t sptr(const void* p) {
    return (uint32_t)__cvta_generic_to_shared(p);
}
__device__ __forceinline__ void ldsm4t(uint32_t& r0, uint32_t& r1,
                                       uint32_t& r2, uint32_t& r3, uint32_t a) {
    asm volatile("ldmatrix.sync.aligned.m8n8.x4.trans.shared.b16 {%0,%1,%2,%3}, [%4];"
                 : "=r"(r0), "=r"(r1), "=r"(r2), "=r"(r3) : "r"(a));
}
__device__ __forceinline__ void ldsm4(uint32_t& r0, uint32_t& r1,
                                      uint32_t& r2, uint32_t& r3, uint32_t a) {
    asm volatile("ldmatrix.sync.aligned.m8n8.x4.shared.b16 {%0,%1,%2,%3}, [%4];"
                 : "=r"(r0), "=r"(r1), "=r"(r2), "=r"(r3) : "r"(a));
}

// ---------------- transpose points + bf16 split (Cpad=16) ------------------
__global__ void k_transpose(const float* __restrict__ pts) {
    int i = blockIdx.x * blockDim.x + threadIdx.x;
    if (i < BATCH * NPTS) {
        int b = i / NPTS, n = i % NPTS;
        #pragma unroll
        for (int c = 0; c < 3; c++) {
            float v = pts[(b * NPTS + n) * 3 + c];
            g_x0[(b * 3 + c) * NPTS + n] = v;
            uint16_t h, l;
            split_bf16(v, h, l);
            g_x0h[(b * 16 + c) * NPTS + n] = h;
            g_x0l[(b * 16 + c) * NPTS + n] = l;
        }
        #pragma unroll
        for (int c = 3; c < 16; c++) {
            g_x0h[(b * 16 + c) * NPTS + n] = 0;
            g_x0l[(b * 16 + c) * NPTS + n] = 0;
        }
    }
}

// ---------------- row norms (fp32 exact) -----------------------------------
__global__ void k_xx(const float* __restrict__ feat, int C, int bstr) {
    int i = blockIdx.x * blockDim.x + threadIdx.x;
    if (i < BATCH * NPTS) {
        int b = i / NPTS, n = i % NPTS;
        const float* f = feat + (size_t)b * bstr + n;
        float s = 0.f;
        for (int c = 0; c < C; c++) { float v = f[(size_t)c * NPTS]; s = fmaf(v, v, s); }
        g_xx[i] = s;
    }
}

// ---------------- w5 bf16 split --------------------------------------------
__global__ void k_cvt_w5(const float* __restrict__ w5) {
    int i = blockIdx.x * blockDim.x + threadIdx.x;
    if (i < 1024 * 512) {
        uint16_t h, l;
        split_bf16(w5[i], h, l);
        g_w5h[i] = h; g_w5l[i] = l;
    }
}

// ---------------- distance GEMM via split-bf16 mma + ldmatrix --------------
// Also emits per-row 64-col chunk maxes to g_smax (for single-pass topk).
__global__ __launch_bounds__(256, 2) void k_dist_mma(
        const uint16_t* __restrict__ srch, const uint16_t* __restrict__ srcl,
        int Ceff, int bstr) {
    __shared__ uint16_t Ah[16 * LDA], Al[16 * LDA];
    __shared__ uint16_t Bh[16 * LDA], Bl[16 * LDA];
    const unsigned FULL = 0xffffffffu;
    int b = blockIdx.z;
    int i0 = blockIdx.y * 128, j0 = blockIdx.x * 128;
    const uint16_t* ph = srch + (size_t)b * bstr;
    const uint16_t* pl = srcl + (size_t)b * bstr;
    int tid = threadIdx.x, lane = tid & 31, warp = tid >> 5;
    int wm = warp & 3, wn = warp >> 2;
    int sub = lane >> 3, Lr = lane & 7;
    float acc[2][8][4];
    #pragma unroll
    for (int mt = 0; mt < 2; mt++)
        #pragma unroll
        for (int nt = 0; nt < 8; nt++)
            #pragma unroll
            for (int q = 0; q < 4; q++) acc[mt][nt][q] = 0.f;

    for (int c0 = 0; c0 < Ceff; c0 += 16) {
        #pragma unroll
        for (int m = 0; m < 4; m++) {
            int idx = m * 256 + tid;
            int mat = idx >> 8, r = (idx >> 4) & 15, q = idx & 15;
            const uint16_t* src = (mat & 1) ? pl : ph;
            int base = (mat & 2) ? j0 : i0;
            uint16_t* dst = (mat == 0) ? Ah : (mat == 1) ? Al : (mat == 2) ? Bh : Bl;
            *(uint4*)&dst[r * LDA + q * 8] =
                *(const uint4*)&src[(size_t)(c0 + r) * NPTS + base + q * 8];
        }
        __syncthreads();
        #pragma unroll
        for (int pass = 0; pass < 3; pass++) {
            const uint16_t* A = (pass == 1) ? Al : Ah;
            const uint16_t* B = (pass == 2) ? Bl : Bh;
            uint32_t af[2][4];
            #pragma unroll
            for (int mt = 0; mt < 2; mt++) {
                int krow = ((sub & 2) ? 8 : 0) + Lr;
                int mcol = wm * 32 + mt * 16 + ((sub & 1) ? 8 : 0);
                ldsm4t(af[mt][0], af[mt][1], af[mt][2], af[mt][3],
                       sptr(A + krow * LDA + mcol));
            }
            uint32_t bf[8][2];
            #pragma unroll
            for (int u = 0; u < 4; u++) {
                int krow = ((sub & 1) ? 8 : 0) + Lr;
                int ncol = wn * 64 + u * 16 + ((sub & 2) ? 8 : 0);
                uint32_t r0, r1, r2, r3;
                ldsm4t(r0, r1, r2, r3, sptr(B + krow * LDA + ncol));
                bf[2 * u][0] = r0; bf[2 * u][1] = r1;
                bf[2 * u + 1][0] = r2; bf[2 * u + 1][1] = r3;
            }
            #pragma unroll
            for (int nt = 0; nt < 8; nt++) {
                mma_bf16(acc[0][nt], af[0], bf[nt][0], bf[nt][1]);
                mma_bf16(acc[1][nt], af[1], bf[nt][0], bf[nt][1]);
            }
        }
        __syncthreads();
    }
    // epilogue: 2*acc - xi - xj -> g_D, plus warp 64-col chunk max -> g_smax
    int g = lane >> 2, t = lane & 3;
    #pragma unroll
    for (int mt = 0; mt < 2; mt++) {
        int r0 = i0 + wm * 32 + mt * 16 + g;
        int r1 = r0 + 8;
        float xi0 = g_xx[b * NPTS + r0];
        float xi1 = g_xx[b * NPTS + r1];
        float m0 = -FLT_MAX, m1 = -FLT_MAX;
        #pragma unroll
        for (int nt = 0; nt < 8; nt++) {
            int j = j0 + wn * 64 + nt * 8 + 2 * t;
            float xj0 = g_xx[b * NPTS + j];
            float xj1 = g_xx[b * NPTS + j + 1];
            float2 v0, v1;
            v0.x = 2.f * acc[mt][nt][0] - xi0 - xj0;
            v0.y = 2.f * acc[mt][nt][1] - xi0 - xj1;
            v1.x = 2.f * acc[mt][nt][2] - xi1 - xj0;
            v1.y = 2.f * acc[mt][nt][3] - xi1 - xj1;
            m0 = fmaxf(m0, fmaxf(v0.x, v0.y));
            m1 = fmaxf(m1, fmaxf(v1.x, v1.y));
            *(float2*)&g_D[((size_t)b * NPTS + r0) * NPTS + j] = v0;
            *(float2*)&g_D[((size_t)b * NPTS + r1) * NPTS + j] = v1;
        }
        m0 = fmaxf(m0, __shfl_xor_sync(FULL, m0, 1));
        m0 = fmaxf(m0, __shfl_xor_sync(FULL, m0, 2));
        m1 = fmaxf(m1, __shfl_xor_sync(FULL, m1, 1));
        m1 = fmaxf(m1, __shfl_xor_sync(FULL, m1, 2));
        if (t == 0) {
            int ch = (j0 >> 6) + wn;
            g_smax[(size_t)(b * NPTS + r0) * 32 + ch] = m0;
            g_smax[(size_t)(b * NPTS + r1) * 32 + ch] = m1;
        }
    }
}

// ---------------- conv5 via split-bf16 mma + fused partial pooling ---------
__global__ __launch_bounds__(256, 2) void k_conv5_mma(
        const float* __restrict__ gam, const float* __restrict__ bet) {
    __shared__ uint16_t Ah[16 * LDA], Al[16 * LDA];
    __shared__ uint16_t Bh[128 * LDB], Bl[128 * LDB];
    __shared__ float sm_max[8][64];
    __shared__ float sm_sum[8][64];
    const unsigned FULL = 0xffffffffu;
    int b = blockIdx.z;
    int n0 = blockIdx.x * 128, o0 = blockIdx.y * 128;
    const uint16_t* ph = g_ch + (size_t)b * CAT_BSTR;
    const uint16_t* pl = g_cl + (size_t)b * CAT_BSTR;
    int tid = threadIdx.x, lane = tid & 31, warp = tid >> 5;
    int wm = warp & 3, wn = warp >> 2;
    int sub = lane >> 3, Lr = lane & 7;
    float acc[2][8][4];
    #pragma unroll
    for (int mt = 0; mt < 2; mt++)
        #pragma unroll
        for (int nt = 0; nt < 8; nt++)
            #pragma unroll
            for (int q = 0; q < 4; q++) acc[mt][nt][q] = 0.f;

    for (int c0 = 0; c0 < 512; c0 += 16) {
        #pragma unroll
        for (int m = 0; m < 4; m++) {
            int idx = m * 256 + tid;
            if (idx < 512) {
                int mat = idx >> 8, r = (idx >> 4) & 15, q = idx & 15;
                const uint16_t* src = mat ? pl : ph;
                uint16_t* dst = mat ? Al : Ah;
                *(uint4*)&dst[r * LDA + q * 8] =
                    *(const uint4*)&src[(size_t)(c0 + r) * NPTS + n0 + q * 8];
            } else {
                int j = idx - 512;
                int mat = j >> 8, row = (j >> 1) & 127, q = j & 1;
                const uint16_t* src = mat ? g_w5l : g_w5h;
                uint16_t* dst = mat ? Bl : Bh;
                *(uint4*)&dst[row * LDB + q * 8] =
                    *(const uint4*)&src[(size_t)(o0 + row) * 512 + c0 + q * 8];
            }
        }
        __syncthreads();
        #pragma unroll
        for (int pass = 0; pass < 3; pass++) {
            const uint16_t* A = (pass == 1) ? Al : Ah;
            const uint16_t* B = (pass == 2) ? Bl : Bh;
            uint32_t af[2][4];
            #pragma unroll
            for (int mt = 0; mt < 2; mt++) {
                int krow = ((sub & 2) ? 8 : 0) + Lr;
                int mcol = wm * 32 + mt * 16 + ((sub & 1) ? 8 : 0);
                ldsm4t(af[mt][0], af[mt][1], af[mt][2], af[mt][3],
                       sptr(A + krow * LDA + mcol));
            }
            uint32_t bf[8][2];
            #pragma unroll
            for (int u = 0; u < 4; u++) {
                int orow = wn * 64 + u * 16 + ((sub & 2) ? 8 : 0) + Lr;
                int kcol = (sub & 1) ? 8 : 0;
                uint32_t r0, r1, r2, r3;
                ldsm4(r0, r1, r2, r3, sptr(B + orow * LDB + kcol));
                bf[2 * u][0] = r0; bf[2 * u][1] = r1;
                bf[2 * u + 1][0] = r2; bf[2 * u + 1][1] = r3;
            }
            #pragma unroll
            for (int nt = 0; nt < 8; nt++) {
                mma_bf16(acc[0][nt], af[0], bf[nt][0], bf[nt][1]);
                mma_bf16(acc[1][nt], af[1], bf[nt][0], bf[nt][1]);
            }
        }
        __syncthreads();
    }
    // epilogue: BN + lrelu, then per-block (max,sum) per channel
    int t = lane & 3;
    float pm[16], ps[16];
    #pragma unroll
    for (int i = 0; i < 16; i++) { pm[i] = -FLT_MAX; ps[i] = 0.f; }
    #pragma unroll
    for (int nt = 0; nt < 8; nt++) {
        int o = o0 + wn * 64 + nt * 8 + 2 * t;
        float sc0 = gam[o] * BN_RSQ, bi0 = bet[o];
        float sc1 = gam[o + 1] * BN_RSQ, bi1 = bet[o + 1];
        #pragma unroll
        for (int mt = 0; mt < 2; mt++) {
            float h0 = lrelu(fmaf(acc[mt][nt][0], sc0, bi0));
            float h1 = lrelu(fmaf(acc[mt][nt][1], sc1, bi1));
            float h2 = lrelu(fmaf(acc[mt][nt][2], sc0, bi0));
            float h3 = lrelu(fmaf(acc[mt][nt][3], sc1, bi1));
            pm[nt * 2] = fmaxf(pm[nt * 2], fmaxf(h0, h2));
            ps[nt * 2] += h0 + h2;
            pm[nt * 2 + 1] = fmaxf(pm[nt * 2 + 1], fmaxf(h1, h3));
            ps[nt * 2 + 1] += h1 + h3;
        }
    }
    #pragma unroll
    for (int i = 0; i < 16; i++) {
        #pragma unroll
        for (int off = 4; off <= 16; off <<= 1) {
            pm[i] = fmaxf(pm[i], __shfl_xor_sync(FULL, pm[i], off));
            ps[i] += __shfl_xor_sync(FULL, ps[i], off);
        }
    }
    if (lane < 4) {
        #pragma unroll
        for (int nt = 0; nt < 8; nt++) {
            #pragma unroll
            for (int p = 0; p < 2; p++) {
                int cc = nt * 8 + 2 * lane + p;
                sm_max[warp][cc] = pm[nt * 2 + p];
                sm_sum[warp][cc] = ps[nt * 2 + p];
            }
        }
    }
    __syncthreads();
    if (tid < 128) {
        int col = tid;
        int w0 = (col >> 6) * 4, cc = col & 63;
        float m = sm_max[w0][cc], s = sm_sum[w0][cc];
        #pragma unroll
        for (int w = 1; w < 4; w++) {
            m = fmaxf(m, sm_max[w0 + w][cc]);
            s += sm_sum[w0 + w][cc];
        }
        size_t base = (size_t)(b * 16 + blockIdx.x) * 1024 + o0 + col;
        g_pmax[base] = m;
        g_psum[base] = s;
    }
}

// ---------------- top-K main: packed-key sorted lists + REDUX pops ---------
// Key = (ord(v) << 32) | (~j): single u64 compare == (value desc, index asc).
// Per-lane 8-deep sorted register list; pops via 2x __reduce_max_sync.
__global__ __launch_bounds__(256) void k_topk() {
    const unsigned FULL = 0xffffffffu;
    int lane = threadIdx.x & 31, warp = threadIdx.x >> 5;
    int row = blockIdx.x * 8 + warp;
    const float4* drow4 = (const float4*)(g_D + (size_t)row * NPTS);

    // Te = 20th largest of 32 precomputed 64-col chunk maxes (<= true 20th)
    float v = g_smax[(size_t)row * 32 + lane];
    #pragma unroll
    for (int k = 2; k <= 32; k <<= 1) {
        #pragma unroll
        for (int j = k >> 1; j > 0; j >>= 1) {
            float o = __shfl_xor_sync(FULL, v, j);
            bool takeMax = (((lane & k) == 0) == ((lane & j) == 0));
            v = takeMax ? fmaxf(v, o) : fminf(v, o);
        }
    }
    float Te = __shfl_sync(FULL, v, KNN - 1);

    // scan with sorted-insert into 8 u64 register keys (desc; sentinel 0)
    unsigned long long kk[SLOTS];
    #pragma unroll
    for (int q = 0; q < SLOTS; q++) kk[q] = 0ull;
    int c = 0;
    #pragma unroll 4
    for (int t = 0; t < NPTS / 128; t++) {
        int jb = t * 128 + lane * 4;
        float4 q4 = drow4[t * 32 + lane];
        float vals[4] = {q4.x, q4.y, q4.z, q4.w};
        #pragma unroll
        for (int m = 0; m < 4; m++) {
            if (vals[m] >= Te) {
                c++;
                unsigned u = __float_as_uint(vals[m]);
                u ^= ((unsigned)((int)u >> 31)) | 0x80000000u;
                unsigned long long p = ((unsigned long long)u << 32)
                                     | (unsigned long long)(0xFFFFFFFFu - (unsigned)(jb + m));
                if (p > kk[SLOTS - 1]) {
                    kk[SLOTS - 1] = p;
                    #pragma unroll
                    for (int q = SLOTS - 1; q > 0; q--) {
                        if (kk[q] > kk[q - 1]) {
                            unsigned long long tmp = kk[q];
                            kk[q] = kk[q - 1];
                            kk[q - 1] = tmp;
                        }
                    }
                }
            }
        }
    }
    unsigned ovm = __ballot_sync(FULL, c > SLOTS);
    if (lane == 0) g_cnt[row] = ovm ? (CAP + 1) : 0;

    if (!ovm) {
        #pragma unroll 1
        for (int k = 0; k < KNN; k++) {
            unsigned hi = (unsigned)(kk[0] >> 32);
            unsigned m = __reduce_max_sync(FULL, hi);
            unsigned lo = (unsigned)kk[0];
            unsigned losel = (hi == m) ? lo : 0u;
            unsigned ml = __reduce_max_sync(FULL, losel);
            if (lane == 0) g_knn[(size_t)row * KNN + k] = (int)(0xFFFFFFFFu - ml);
            if (hi == m && lo == ml) {
                #pragma unroll
                for (int q = 0; q < SLOTS - 1; q++) kk[q] = kk[q + 1];
                kk[SLOTS - 1] = 0ull;
            }
        }
    }
    // overflow rows handled by k_topk_fb
}

// ---------------- top-K fallback: exact full-row path (rarely runs) --------
__global__ void k_topk_fb() {
    const unsigned FULL = 0xffffffffu;
    int lane = threadIdx.x & 31, warp = threadIdx.x >> 5;
    int row = blockIdx.x * 8 + warp;
    if (g_cnt[row] <= CAP) return;      // warp-uniform: whole warp exits

    const float* drow = g_D + (size_t)row * NPTS;
    float arr[KNN]; int ai[KNN];
    #pragma unroll
    for (int q = 0; q < KNN; q++) { arr[q] = -FLT_MAX; ai[q] = 0x7FFFFFFF; }
    #pragma unroll 1
    for (int t = 0; t < NPTS / 128; t++) {
        int jb = t * 128 + lane * 4;
        float4 v4 = *(const float4*)&drow[jb];
        float vv[4] = {v4.x, v4.y, v4.z, v4.w};
        #pragma unroll
        for (int m = 0; m < 4; m++) {
            float vx = vv[m];
            if (vx > arr[0]) {
                arr[0] = vx; ai[0] = jb + m;
                #pragma unroll
                for (int q = 0; q < KNN - 1; q++) {
                    if (arr[q + 1] < arr[q]) {
                        float tv = arr[q]; arr[q] = arr[q + 1]; arr[q + 1] = tv;
                        int ti = ai[q]; ai[q] = ai[q + 1]; ai[q + 1] = ti;
                    }
                }
            }
        }
    }
    #pragma unroll 1
    for (int k = 0; k < KNN; k++) {
        float cvv = arr[KNN - 1]; int cii = ai[KNN - 1];
        float wv = cvv; int wi = cii;
        #pragma unroll
        for (int s = 16; s > 0; s >>= 1) {
            float ov = __shfl_xor_sync(FULL, wv, s);
            int   oi = __shfl_xor_sync(FULL, wi, s);
            if (ov > wv || (ov == wv && oi < wi)) { wv = ov; wi = oi; }
        }
        if (lane == 0) g_knn[(size_t)row * KNN + k] = wi;
        if (cii == wi) {
            #pragma unroll
            for (int q = KNN - 1; q > 0; q--) { arr[q] = arr[q - 1]; ai[q] = ai[q - 1]; }
            arr[0] = -FLT_MAX; ai[0] = 0x7FFFFFFF;
        }
    }
}

// ---------------- Y = W2 X, Z = (W1-W2) X (fp32) ---------------------------
__global__ void k_yz(const float* __restrict__ feat, const float* __restrict__ W,
                     int C, int Cout, int bstr) {
    __shared__ float As[16][64];
    __shared__ float B1[16][64];
    __shared__ float B2[16][64];
    int b = blockIdx.z;
    int n0 = blockIdx.x * 64, o0 = blockIdx.y * 64;
    const float* fb = feat + (size_t)b * bstr;
    int tx = threadIdx.x & 15, ty = threadIdx.x >> 4;
    float aU[4][4] = {}, aY[4][4] = {};
    for (int c0 = 0; c0 < C; c0 += 16) {
        for (int e = threadIdx.x; e < 1024; e += 256) {
            int kk = e >> 6, nn = e & 63;
            int c = c0 + kk;
            As[kk][nn] = (c < C) ? fb[(size_t)c * NPTS + n0 + nn] : 0.f;
        }
        for (int e = threadIdx.x; e < 1024; e += 256) {
            int kk = e & 15, oo = e >> 4;
            int c = c0 + kk;
            float w1 = 0.f, w2 = 0.f;
            if (c < C) {
                const float* wr = W + (size_t)(o0 + oo) * (2 * C);
                w1 = wr[c]; w2 = wr[C + c];
            }
            B1[kk][oo] = w1; B2[kk][oo] = w2;
        }
        __syncthreads();
        #pragma unroll
        for (int kk = 0; kk < 16; kk++) {
            float4 a4 = *(const float4*)&As[kk][ty * 4];
            float4 b14 = *(const float4*)&B1[kk][tx * 4];
            float4 b24 = *(const float4*)&B2[kk][tx * 4];
            float av[4] = {a4.x, a4.y, a4.z, a4.w};
            float b1v[4] = {b14.x, b14.y, b14.z, b14.w};
            float b2v[4] = {b24.x, b24.y, b24.z, b24.w};
            #pragma unroll
            for (int r = 0; r < 4; r++)
                #pragma unroll
                for (int s = 0; s < 4; s++) {
                    aU[r][s] = fmaf(av[r], b1v[s], aU[r][s]);
                    aY[r][s] = fmaf(av[r], b2v[s], aY[r][s]);
                }
        }
        __syncthreads();
    }
    #pragma unroll
    for (int r = 0; r < 4; r++) {
        int n = n0 + ty * 4 + r;
        size_t base = ((size_t)b * NPTS + n) * 256 + o0 + tx * 4;
        float4 y, z;
        y.x = aY[r][0]; y.y = aY[r][1]; y.z = aY[r][2]; y.w = aY[r][3];
        z.x = aU[r][0] - y.x; z.y = aU[r][1] - y.y;
        z.z = aU[r][2] - y.z; z.w = aU[r][3] - y.w;
        *(float4*)&g_Y[base] = y;
        *(float4*)&g_Z[base] = z;
    }
}

// ---------------- gather-max + BN + lrelu -> xcat + bf16 mirrors -----------
__global__ void k_gather(float* __restrict__ out, const float* __restrict__ gam,
                         const float* __restrict__ bet, int Cout, int co) {
    __shared__ int   sidx[32 * KNN];
    __shared__ float sout[256 * 33];
    int b = blockIdx.y, n0 = blockIdx.x * 32;
    for (int e = threadIdx.x; e < 32 * KNN; e += blockDim.x)
        sidx[e] = g_knn[((size_t)b * NPTS + n0) * KNN + e];
    __syncthreads();
    int o = threadIdx.x;
    float sc = gam[o] * BN_RSQ, bi = bet[o];
    const float* Yb = g_Y + (size_t)b * NPTS * 256;
    const float* Zb = g_Z + (size_t)b * NPTS * 256;
    for (int nn = 0; nn < 32; nn++) {
        float m = -FLT_MAX;
        #pragma unroll
        for (int k = 0; k < KNN; k++) {
            int j = sidx[nn * KNN + k];
            m = fmaxf(m, Yb[(size_t)j * 256 + o]);
        }
        float v = Zb[(size_t)(n0 + nn) * 256 + o] + m;
        v = lrelu(fmaf(v, sc, bi));
        sout[o * 33 + nn] = v;
    }
    __syncthreads();
    float* ob = out + (size_t)b * CAT_BSTR;
    for (int e = threadIdx.x; e < Cout * 32; e += blockDim.x) {
        int oo = e >> 5, nn = e & 31;
        float v = sout[oo * 33 + nn];
        ob[(size_t)oo * NPTS + n0 + nn] = v;
        uint16_t h, l;
        split_bf16(v, h, l);
        size_t bidx = ((size_t)b * 512 + co + oo) * NPTS + n0 + nn;
        g_ch[bidx] = h;
        g_cl[bidx] = l;
    }
}

// ---------------- final pool from conv5 partials -> g_f --------------------
__global__ void k_pool2() {
    int b = blockIdx.y;
    int o = blockIdx.x * 256 + threadIdx.x;
    float m = -FLT_MAX, s = 0.f;
    #pragma unroll
    for (int nt = 0; nt < 16; nt++) {
        size_t base = (size_t)(b * 16 + nt) * 1024 + o;
        m = fmaxf(m, g_pmax[base]);
        s += g_psum[base];
    }
    g_f[b * 2048 + o] = m;
    g_f[b * 2048 + 1024 + o] = s * (1.0f / NPTS);
}

// ---------------- fc1: 2048->512, BN + lrelu -------------------------------
__global__ void k_fc1(const float* __restrict__ fw, const float* __restrict__ fb,
                      const float* __restrict__ gam, const float* __restrict__ bet) {
    int b = blockIdx.y;
    int w = threadIdx.x >> 5, lane = threadIdx.x & 31;
    int o = blockIdx.x * 8 + w;
    const float* f = g_f + b * 2048;
    const float* wr = fw + (size_t)o * 2048;
    float acc = 0.f;
    for (int c = lane; c < 2048; c += 32) acc = fmaf(f[c], wr[c], acc);
    #pragma unroll
    for (int s = 16; s > 0; s >>= 1) acc += __shfl_xor_sync(0xffffffffu, acc, s);
    if (lane == 0) {
        float v = acc + fb[o];
        v = lrelu(fmaf(v, gam[o] * BN_RSQ, bet[o]));
        g_fc1[b * 512 + o] = v;
    }
}

// ---------------- fc2: 512->256, BN (no lrelu) -> d_out --------------------
__global__ void k_fc2(const float* __restrict__ fw, const float* __restrict__ fb,
                      const float* __restrict__ gam, const float* __restrict__ bet,
                      float* __restrict__ out) {
    int b = blockIdx.y;
    int w = threadIdx.x >> 5, lane = threadIdx.x & 31;
    int o = blockIdx.x * 8 + w;
    const float* f = g_fc1 + b * 512;
    const float* wr = fw + (size_t)o * 512;
    float acc = 0.f;
    for (int c = lane; c < 512; c += 32) acc = fmaf(f[c], wr[c], acc);
    #pragma unroll
    for (int s = 16; s > 0; s >>= 1) acc += __shfl_xor_sync(0xffffffffu, acc, s);
    if (lane == 0) {
        float v = acc + fb[o];
        out[b * 256 + o] = fmaf(v, gam[o] * BN_RSQ, bet[o]);
    }
}

// ---------------- driver ---------------------------------------------------
static void run_edge(const float* feat, int C, int bstr,
                     const uint16_t* dh, const uint16_t* dl, int Ceff, int bfstr,
                     const float* W, const float* gam, const float* bet,
                     float* out, int Cout, int co) {
    k_xx<<<(BATCH * NPTS + 255) / 256, 256>>>(feat, C, bstr);
    k_dist_mma<<<dim3(NPTS / 128, NPTS / 128, BATCH), 256>>>(dh, dl, Ceff, bfstr);
    k_topk<<<BATCH * NPTS / 8, 256>>>();
    k_topk_fb<<<BATCH * NPTS / 8, 256>>>();
    k_yz<<<dim3(NPTS / 64, Cout / 64, BATCH), 256>>>(feat, W, C, Cout, bstr);
    k_gather<<<dim3(NPTS / 32, BATCH), Cout>>>(out, gam, bet, Cout, co);
}

extern "C" void kernel_launch(void* const* d_in, const int* in_sizes, int n_in,
                              void* d_out, int out_size) {
    const float* pts = (const float*)d_in[0];
    const float* w1 = (const float*)d_in[1];
    const float* g1 = (const float*)d_in[2];
    const float* b1 = (const float*)d_in[3];
    const float* w2 = (const float*)d_in[4];
    const float* g2 = (const float*)d_in[5];
    const float* b2 = (const float*)d_in[6];
    const float* w3 = (const float*)d_in[7];
    const float* g3 = (const float*)d_in[8];
    const float* b3 = (const float*)d_in[9];
    const float* w4 = (const float*)d_in[10];
    const float* g4 = (const float*)d_in[11];
    const float* b4 = (const float*)d_in[12];
    const float* w5 = (const float*)d_in[13];
    const float* g5 = (const float*)d_in[14];
    const float* b5 = (const float*)d_in[15];
    const float* fw1 = (const float*)d_in[16];
    const float* fb1 = (const float*)d_in[17];
    const float* g6 = (const float*)d_in[18];
    const float* b6 = (const float*)d_in[19];
    const float* fw2 = (const float*)d_in[20];
    const float* fb2 = (const float*)d_in[21];
    const float* g7 = (const float*)d_in[22];
    const float* b7 = (const float*)d_in[23];

    float *x0, *xcat;
    uint16_t *x0h, *x0l, *ch, *cl;
    cudaGetSymbolAddress((void**)&x0, g_x0);
    cudaGetSymbolAddress((void**)&xcat, g_xcat);
    cudaGetSymbolAddress((void**)&x0h, g_x0h);
    cudaGetSymbolAddress((void**)&x0l, g_x0l);
    cudaGetSymbolAddress((void**)&ch, g_ch);
    cudaGetSymbolAddress((void**)&cl, g_cl);
    float* x1 = xcat;                  // ch 0..63
    float* x2 = xcat + 64 * NPTS;      // ch 64..127
    float* x3 = xcat + 128 * NPTS;     // ch 128..255
    float* x4 = xcat + 256 * NPTS;     // ch 256..511

    k_transpose<<<(BATCH * NPTS + 255) / 256, 256>>>(pts);
    run_edge(x0, 3,   3 * NPTS, x0h, x0l, 16, 16 * NPTS,
             w1, g1, b1, x1, 64, 0);
    run_edge(x1, 64,  CAT_BSTR, ch,              cl,              64,  CAT_BSTR,
             w2, g2, b2, x2, 64, 64);
    run_edge(x2, 64,  CAT_BSTR, ch + 64 * NPTS,  cl + 64 * NPTS,  64,  CAT_BSTR,
             w3, g3, b3, x3, 128, 128);
    run_edge(x3, 128, CAT_BSTR, ch + 128 * NPTS, cl + 128 * NPTS, 128, CAT_BSTR,
             w4, g4, b4, x4, 256, 256);
    k_cvt_w5<<<(1024 * 512 + 255) / 256, 256>>>(w5);
    k_conv5_mma<<<dim3(NPTS / 128, 1024 / 128, BATCH), 256>>>(g5, b5);
    k_pool2<<<dim3(1024 / 256, BATCH), 256>>>();
    k_fc1<<<dim3(512 / 8, BATCH), 256>>>(fw1, fb1, g6, b6);
    k_fc2<<<dim3(256 / 8, BATCH), 256>>>(fw2, fb2, g7, b7, (float*)d_out);
}